// round 1
// baseline (speedup 1.0000x reference)
#include <cuda_runtime.h>

// RNN_43920335569315: vanilla tanh RNN
//   B=8192, T=512, I=H=7, O=1
//   h_t = tanh(x_t W_ih^T + b_ih + b_hh + h_{t-1} W_hh^T)
//   out[b,t] = h_t . W_fc + b_fc ;  hidden = h_T
//
// Layout assumptions (metadata order): d_in = {x, W_ih, W_hh, b_ih, b_hh, W_fc, b_fc}
// d_out = concat(out [B,T], hidden [1,B,H]) flattened.

#define RNN_B 8192
#define RNN_T 512
#define RNN_H 7

// Accurate-enough tanh: 1 - 2/(exp(2x)+1).
// exp overflow -> inf -> rcp -> 0 -> +1; underflow -> 0 -> -1. Correct limits, no branches.
__device__ __forceinline__ float fast_tanhf(float x) {
    float e = __expf(2.0f * x);              // FMUL + MUFU.EX2
    return 1.0f - __fdividef(2.0f, e + 1.0f); // FADD + MUFU.RCP + FMUL + FADD
}

__global__ void __launch_bounds__(32, 1) rnn_fused_kernel(
    const float* __restrict__ x,
    const float* __restrict__ W_ih,
    const float* __restrict__ W_hh,
    const float* __restrict__ b_ih,
    const float* __restrict__ b_hh,
    const float* __restrict__ W_fc,
    const float* __restrict__ b_fc,
    float* __restrict__ out,
    float* __restrict__ hidden)
{
    const int b = blockIdx.x * 32 + threadIdx.x;
    if (b >= RNN_B) return;

    // ---- weights into registers (uniform across threads; L1-broadcast loads) ----
    float wih[RNN_H][RNN_H], whh[RNN_H][RNN_H], bc[RNN_H], wfc[RNN_H];
#pragma unroll
    for (int j = 0; j < RNN_H; ++j) {
#pragma unroll
        for (int i = 0; i < RNN_H; ++i) {
            wih[j][i] = __ldg(&W_ih[j * RNN_H + i]);
            whh[j][i] = __ldg(&W_hh[j * RNN_H + i]);
        }
        bc[j]  = __ldg(&b_ih[j]) + __ldg(&b_hh[j]);
        wfc[j] = __ldg(&W_fc[j]);
    }
    const float bo = __ldg(&b_fc[0]);

    // Per-thread x stream: x + b*T*7 floats.  b*T*7*4 = b*14336 bytes -> 128B aligned.
    // Read as aligned float4: 7 x float4 = 28 floats = 4 timesteps per "group".
    const float4* __restrict__ xq =
        reinterpret_cast<const float4*>(x + (size_t)b * RNN_T * RNN_H);

    float h[RNN_H];
#pragma unroll
    for (int j = 0; j < RNN_H; ++j) h[j] = 0.0f;

    // Double-buffered group loads: cur holds group g, nxt prefetches g+1.
    float cur[28], nxt[28];
#pragma unroll
    for (int q = 0; q < 7; ++q)
        reinterpret_cast<float4*>(cur)[q] = __ldg(&xq[q]);

    float* __restrict__ outp = out + (size_t)b * RNN_T;

    const int NGROUPS = RNN_T / 4;  // 128
    for (int g = 0; g < NGROUPS; ++g) {
        // L2 prefetch 2 groups ahead (cheap; covers the DRAM leg).
        if (g + 2 < NGROUPS) {
            const float4* pf = &xq[(size_t)(g + 2) * 7];
            asm volatile("prefetch.global.L2 [%0];" :: "l"(pf));
        }
        // Issue next group's loads early (L1/L2 leg hidden under ~4 steps of compute).
        if (g + 1 < NGROUPS) {
#pragma unroll
            for (int q = 0; q < 7; ++q)
                reinterpret_cast<float4*>(nxt)[q] = __ldg(&xq[(size_t)(g + 1) * 7 + q]);
        }

        float4 ov;
        float* ovp = reinterpret_cast<float*>(&ov);

#pragma unroll
        for (int s = 0; s < 4; ++s) {
            const float* xv = cur + s * RNN_H;
            float acc[RNN_H];
#pragma unroll
            for (int j = 0; j < RNN_H; ++j) {
                float a = bc[j];
#pragma unroll
                for (int i = 0; i < RNN_H; ++i) a = fmaf(wih[j][i], xv[i], a);
#pragma unroll
                for (int k = 0; k < RNN_H; ++k) a = fmaf(whh[j][k], h[k], a);
                acc[j] = a;
            }
            float o = bo;
#pragma unroll
            for (int j = 0; j < RNN_H; ++j) {
                h[j] = fast_tanhf(acc[j]);
                o = fmaf(wfc[j], h[j], o);
            }
            ovp[s] = o;
        }

        // out[b, 4g .. 4g+3] : 16B-aligned vector store.
        *reinterpret_cast<float4*>(outp + g * 4) = ov;

#pragma unroll
        for (int q = 0; q < 28; ++q) cur[q] = nxt[q];
    }

    // hidden [1, B, H]
    if (hidden) {
#pragma unroll
        for (int j = 0; j < RNN_H; ++j)
            hidden[(size_t)b * RNN_H + j] = h[j];
    }
}

extern "C" void kernel_launch(void* const* d_in, const int* in_sizes, int n_in,
                              void* d_out, int out_size) {
    const float* x    = (const float*)d_in[0];
    const float* W_ih = (const float*)d_in[1];
    const float* W_hh = (const float*)d_in[2];
    const float* b_ih = (const float*)d_in[3];
    const float* b_hh = (const float*)d_in[4];
    const float* W_fc = (const float*)d_in[5];
    const float* b_fc = (const float*)d_in[6];

    float* out = (float*)d_out;
    // Output = concat(out [B,T], hidden [1,B,H]) if the harness sized it that way.
    float* hidden = nullptr;
    if (out_size >= RNN_B * RNN_T + RNN_B * RNN_H)
        hidden = out + (size_t)RNN_B * RNN_T;

    dim3 grid(RNN_B / 32);   // 256 blocks of 32 -> spread warps across the 148 SMs
    dim3 block(32);
    rnn_fused_kernel<<<grid, block>>>(x, W_ih, W_hh, b_ih, b_hh, W_fc, b_fc,
                                      out, hidden);
}

// round 2
// speedup vs baseline: 1.3881x; 1.3881x over previous
#include <cuda_runtime.h>

// RNN_43920335569315: vanilla tanh RNN. B=8192, T=512, I=H=7, O=1.
//   h_t = tanh(x_t W_ih^T + b_ih + b_hh + h_{t-1} W_hh^T);  out = h.W_fc + b_fc
// d_in = {x, W_ih, W_hh, b_ih, b_hh, W_fc, b_fc};  d_out = concat(out[B,T], h_T[1,B,H]).
//
// Round-2 design: 2 lanes per batch element (16 elems/warp, 512 warps -> 86% SMSP
// coverage), packed fma.rn.f32x2 row-pair accumulators, tanh.approx.f32,
// SHFL.BFLY hidden-state exchange consumed last to hide shuffle latency.

#define RNN_B 8192
#define RNN_T 512
#define RNN_H 7

typedef unsigned long long u64;

__device__ __forceinline__ u64 pk2(float lo, float hi) {
    u64 r; asm("mov.b64 %0, {%1, %2};" : "=l"(r) : "f"(lo), "f"(hi)); return r;
}
__device__ __forceinline__ void upk2(u64 v, float& lo, float& hi) {
    asm("mov.b64 {%0, %1}, %2;" : "=f"(lo), "=f"(hi) : "l"(v));
}
__device__ __forceinline__ u64 fma2(u64 a, u64 b, u64 c) {
    u64 d; asm("fma.rn.f32x2 %0, %1, %2, %3;" : "=l"(d) : "l"(a), "l"(b), "l"(c)); return d;
}
__device__ __forceinline__ float tanh_ap(float x) {
    float y; asm("tanh.approx.f32 %0, %1;" : "=f"(y) : "f"(x)); return y;
}

__global__ void __launch_bounds__(32, 1) rnn_fused_kernel(
    const float* __restrict__ x,
    const float* __restrict__ W_ih,
    const float* __restrict__ W_hh,
    const float* __restrict__ b_ih,
    const float* __restrict__ b_hh,
    const float* __restrict__ W_fc,
    const float* __restrict__ b_fc,
    float* __restrict__ out,
    float* __restrict__ hidden)
{
    const int lane = threadIdx.x;
    const int half = lane & 1;               // 0: rows 0-3, 1: rows 4-6 (+pad row 7)
    const int b    = blockIdx.x * 16 + (lane >> 1);   // batch element (shared by lane pair)

    const int base = half * 4;               // first row this lane owns
    const int rbas = (1 - half) * 4;         // first row the partner owns (remote k base)

    // ---- per-lane weights, packed over the two row-pairs {base,base+1},{base+2,base+3} ----
    // Row index >= 7 is a pad row: weights/bias forced to 0 -> acc stays 0, tanh(0)=0.
    float wih_s[4][RNN_H];      // [local row m][i]
    float whh_loc[4][4];        // [local row m][local k m2]   k = base + m2
    float whh_rem[4][4];        // [local row m][remote k m2]  k = rbas + m2
    float bc_s[4];
#pragma unroll
    for (int m = 0; m < 4; ++m) {
        const int r = base + m;
        const bool ok = (r < RNN_H);
#pragma unroll
        for (int i = 0; i < RNN_H; ++i)
            wih_s[m][i] = ok ? __ldg(&W_ih[r * RNN_H + i]) : 0.0f;
#pragma unroll
        for (int m2 = 0; m2 < 4; ++m2) {
            const int kl = base + m2, kr = rbas + m2;
            whh_loc[m][m2] = (ok && kl < RNN_H) ? __ldg(&W_hh[r * RNN_H + kl]) : 0.0f;
            whh_rem[m][m2] = (ok && kr < RNN_H) ? __ldg(&W_hh[r * RNN_H + kr]) : 0.0f;
        }
        bc_s[m] = ok ? (__ldg(&b_ih[r]) + __ldg(&b_hh[r])) : 0.0f;
    }

    // Pack into f32x2 operands: pack p covers rows (base+2p, base+2p+1).
    u64 wih_p[2][RNN_H], whl_p[2][4], whr_p[2][4], bias_p[2];
#pragma unroll
    for (int p = 0; p < 2; ++p) {
#pragma unroll
        for (int i = 0; i < RNN_H; ++i)
            wih_p[p][i] = pk2(wih_s[2 * p][i], wih_s[2 * p + 1][i]);
#pragma unroll
        for (int m2 = 0; m2 < 4; ++m2) {
            whl_p[p][m2] = pk2(whh_loc[2 * p][m2], whh_loc[2 * p + 1][m2]);
            whr_p[p][m2] = pk2(whh_rem[2 * p][m2], whh_rem[2 * p + 1][m2]);
        }
        bias_p[p] = pk2(bc_s[2 * p], bc_s[2 * p + 1]);
    }

    // fc weights reordered the same way: local t[m] <-> k=base+m, remote s[m] <-> k=rbas+m.
    float wfc_l[4], wfc_r[4];
#pragma unroll
    for (int m = 0; m < 4; ++m) {
        const int kl = base + m, kr = rbas + m;
        wfc_l[m] = (kl < RNN_H) ? __ldg(&W_fc[kl]) : 0.0f;
        wfc_r[m] = (kr < RNN_H) ? __ldg(&W_fc[kr]) : 0.0f;
    }
    const float bo = __ldg(&b_fc[0]);

    // ---- x stream: both lanes of a pair read the same element (coalesced/broadcast) ----
    const float4* __restrict__ xq =
        reinterpret_cast<const float4*>(x + (size_t)b * RNN_T * RNN_H);

    float t[4] = {0.f, 0.f, 0.f, 0.f};   // this lane's h values (rows base..base+3)
    float s[4] = {0.f, 0.f, 0.f, 0.f};   // partner's h values (rows rbas..rbas+3)

    float cur[28], nxt[28];
#pragma unroll
    for (int q = 0; q < 7; ++q)
        reinterpret_cast<float4*>(cur)[q] = __ldg(&xq[q]);

    float* __restrict__ outp = out + (size_t)b * RNN_T;

    const int NGROUPS = RNN_T / 4;  // 128
    for (int g = 0; g < NGROUPS; ++g) {
        if (g + 2 < NGROUPS) {
            const float4* pf = &xq[(size_t)(g + 2) * 7];
            asm volatile("prefetch.global.L2 [%0];" :: "l"(pf));
        }
        if (g + 1 < NGROUPS) {
#pragma unroll
            for (int q = 0; q < 7; ++q)
                reinterpret_cast<float4*>(nxt)[q] = __ldg(&xq[(size_t)(g + 1) * 7 + q]);
        }

        float4 ov;
        float* ovp = reinterpret_cast<float*>(&ov);

#pragma unroll
        for (int st = 0; st < 4; ++st) {
            const float* xv = cur + st * RNN_H;

            u64 acc0 = bias_p[0], acc1 = bias_p[1];
            // x projection (independent of h)
#pragma unroll
            for (int i = 0; i < RNN_H; ++i) {
                const u64 xb = pk2(xv[i], xv[i]);
                acc0 = fma2(wih_p[0][i], xb, acc0);
                acc1 = fma2(wih_p[1][i], xb, acc1);
            }
            // recurrent, local h first (no shuffle dependency)...
#pragma unroll
            for (int m = 0; m < 4; ++m) {
                const u64 hb = pk2(t[m], t[m]);
                acc0 = fma2(whl_p[0][m], hb, acc0);
                acc1 = fma2(whl_p[1][m], hb, acc1);
            }
            // ...remote h last (hides SHFL latency from previous step)
#pragma unroll
            for (int m = 0; m < 4; ++m) {
                const u64 hb = pk2(s[m], s[m]);
                acc0 = fma2(whr_p[0][m], hb, acc0);
                acc1 = fma2(whr_p[1][m], hb, acc1);
            }

            float a0, a1, a2, a3;
            upk2(acc0, a0, a1);
            upk2(acc1, a2, a3);
            t[0] = tanh_ap(a0);
            t[1] = tanh_ap(a1);
            t[2] = tanh_ap(a2);
            t[3] = tanh_ap(a3);

            // exchange with partner lane
            s[0] = __shfl_xor_sync(0xFFFFFFFFu, t[0], 1);
            s[1] = __shfl_xor_sync(0xFFFFFFFFu, t[1], 1);
            s[2] = __shfl_xor_sync(0xFFFFFFFFu, t[2], 1);
            s[3] = __shfl_xor_sync(0xFFFFFFFFu, t[3], 1);

            // output dot (pad entries have zero weight)
            float o = bo;
#pragma unroll
            for (int m = 0; m < 4; ++m) o = fmaf(wfc_l[m], t[m], o);
#pragma unroll
            for (int m = 0; m < 4; ++m) o = fmaf(wfc_r[m], s[m], o);
            ovp[st] = o;
        }

        if (half == 0)   // one store per element
            *reinterpret_cast<float4*>(outp + g * 4) = ov;

#pragma unroll
        for (int q = 0; q < 28; ++q) cur[q] = nxt[q];
    }

    // hidden [1, B, H]: each lane writes its own (real) rows
    if (hidden) {
        float* hp = hidden + (size_t)b * RNN_H;
#pragma unroll
        for (int m = 0; m < 4; ++m) {
            const int r = base + m;
            if (r < RNN_H) hp[r] = t[m];
        }
    }
}

extern "C" void kernel_launch(void* const* d_in, const int* in_sizes, int n_in,
                              void* d_out, int out_size) {
    const float* x    = (const float*)d_in[0];
    const float* W_ih = (const float*)d_in[1];
    const float* W_hh = (const float*)d_in[2];
    const float* b_ih = (const float*)d_in[3];
    const float* b_hh = (const float*)d_in[4];
    const float* W_fc = (const float*)d_in[5];
    const float* b_fc = (const float*)d_in[6];

    float* out = (float*)d_out;
    float* hidden = nullptr;
    if (out_size >= RNN_B * RNN_T + RNN_B * RNN_H)
        hidden = out + (size_t)RNN_B * RNN_T;

    dim3 grid(RNN_B / 16);   // 512 single-warp blocks -> ~86% SMSP coverage
    dim3 block(32);
    rnn_fused_kernel<<<grid, block>>>(x, W_ih, W_hh, b_ih, b_hh, W_fc, b_fc,
                                      out, hidden);
}

// round 3
// speedup vs baseline: 1.4302x; 1.0304x over previous
#include <cuda_runtime.h>

// RNN_43920335569315: vanilla tanh RNN. B=8192, T=512, I=H=7, O=1.
//   h_t = tanh(x_t W_ih^T + b_ih + b_hh + h_{t-1} W_hh^T);  out = h.W_fc + b_fc
// d_in = {x, W_ih, W_hh, b_ih, b_hh, W_fc, b_fc};  d_out = concat(out[B,T], h_T[1,B,H]).
//
// Round-3: 2 lanes/element (512 warps), horizontal f32x2 k-pairing -> 4 independent
// depth-4 FMA chains per step, 4-step base precompute as stall filler, local-h FMAs
// overlapped with SHFL flight, ping-pong x buffers (no copy loop).

#define RNN_B 8192
#define RNN_T 512
#define RNN_H 7

typedef unsigned long long u64;

__device__ __forceinline__ u64 pk2(float lo, float hi) {
    u64 r; asm("mov.b64 %0, {%1, %2};" : "=l"(r) : "f"(lo), "f"(hi)); return r;
}
__device__ __forceinline__ void upk2(u64 v, float& lo, float& hi) {
    asm("mov.b64 {%0, %1}, %2;" : "=f"(lo), "=f"(hi) : "l"(v));
}
__device__ __forceinline__ u64 fma2(u64 a, u64 b, u64 c) {
    u64 d; asm("fma.rn.f32x2 %0, %1, %2, %3;" : "=l"(d) : "l"(a), "l"(b), "l"(c)); return d;
}
__device__ __forceinline__ float tanh_ap(float x) {
    float y; asm("tanh.approx.f32 %0, %1;" : "=f"(y) : "f"(x)); return y;
}

__global__ void __launch_bounds__(32, 1) rnn_fused_kernel(
    const float* __restrict__ x,
    const float* __restrict__ W_ih,
    const float* __restrict__ W_hh,
    const float* __restrict__ b_ih,
    const float* __restrict__ b_hh,
    const float* __restrict__ W_fc,
    const float* __restrict__ b_fc,
    float* __restrict__ out,
    float* __restrict__ hidden)
{
    const int lane = threadIdx.x;
    const int half = lane & 1;                       // 0: rows 0-3, 1: rows 4-6(+pad)
    const int b    = blockIdx.x * 16 + (lane >> 1);

    const int base = half * 4;                       // my first row
    const int rbas = (1 - half) * 4;                 // partner's first row

    // k-pair column order seen by this lane: [local0, local1, remote0, remote1]
    const int kp0[4] = { base, base + 2, rbas, rbas + 2 };

    // ---- weights packed along k/i pairs ----
    u64 wihp[4][4];   // [my row m][i-pair p] = (W_ih[r][2p], W_ih[r][2p+1])
    u64 whhp[4][4];   // [my row m][k-pair p] per kp0 order
    float bias_m[4];
#pragma unroll
    for (int m = 0; m < 4; ++m) {
        const int r = base + m;
        const bool ok = (r < RNN_H);
#pragma unroll
        for (int p = 0; p < 4; ++p) {
            const int i0 = 2 * p, i1 = 2 * p + 1;
            float a = (ok && i0 < RNN_H) ? __ldg(&W_ih[r * RNN_H + i0]) : 0.0f;
            float c = (ok && i1 < RNN_H) ? __ldg(&W_ih[r * RNN_H + i1]) : 0.0f;
            wihp[m][p] = pk2(a, c);
            const int k0 = kp0[p], k1 = kp0[p] + 1;
            float d = (ok && k0 < RNN_H) ? __ldg(&W_hh[r * RNN_H + k0]) : 0.0f;
            float e = (ok && k1 < RNN_H) ? __ldg(&W_hh[r * RNN_H + k1]) : 0.0f;
            whhp[m][p] = pk2(d, e);
        }
        bias_m[m] = ok ? (__ldg(&b_ih[r]) + __ldg(&b_hh[r])) : 0.0f;
    }
    u64 wfcp[4];      // same k-pair order
#pragma unroll
    for (int p = 0; p < 4; ++p) {
        const int k0 = kp0[p], k1 = kp0[p] + 1;
        float a = (k0 < RNN_H) ? __ldg(&W_fc[k0]) : 0.0f;
        float c = (k1 < RNN_H) ? __ldg(&W_fc[k1]) : 0.0f;
        wfcp[p] = pk2(a, c);
    }
    const float bo = __ldg(&b_fc[0]);

    const float4* __restrict__ xq =
        reinterpret_cast<const float4*>(x + (size_t)b * RNN_T * RNN_H);
    float* __restrict__ outp = out + (size_t)b * RNN_T;

    float t0 = 0.f, t1 = 0.f, t2 = 0.f, t3 = 0.f;    // my h rows
    // h packs carried across steps (k-pair layout): local pairs, remote pairs
    u64 hL0 = 0, hL1 = 0, hR0 = 0, hR1 = 0;

    float bufA[28], bufB[28];
#pragma unroll
    for (int q = 0; q < 7; ++q)
        reinterpret_cast<float4*>(bufA)[q] = __ldg(&xq[q]);

#define LOAD_GROUP(BUF, G) do {                                             \
        _Pragma("unroll")                                                   \
        for (int q = 0; q < 7; ++q)                                         \
            reinterpret_cast<float4*>(BUF)[q] = __ldg(&xq[(size_t)(G) * 7 + q]); \
    } while (0)

#define PROCESS_GROUP(BUF, G) do {                                          \
        /* base pairs for all 4 steps: independent stall filler */          \
        u64 basep[4][4];                                                    \
        _Pragma("unroll")                                                   \
        for (int st = 0; st < 4; ++st) {                                    \
            const float* xv = (BUF) + st * RNN_H;                           \
            const u64 xp0 = pk2(xv[0], xv[1]);                              \
            const u64 xp1 = pk2(xv[2], xv[3]);                              \
            const u64 xp2 = pk2(xv[4], xv[5]);                              \
            const u64 xp3 = pk2(xv[6], 0.0f);                               \
            _Pragma("unroll")                                               \
            for (int m = 0; m < 4; ++m) {                                   \
                u64 a = pk2(bias_m[m], 0.0f);                               \
                a = fma2(wihp[m][0], xp0, a);                               \
                a = fma2(wihp[m][1], xp1, a);                               \
                a = fma2(wihp[m][2], xp2, a);                               \
                a = fma2(wihp[m][3], xp3, a);                               \
                basep[st][m] = a;                                           \
            }                                                               \
        }                                                                   \
        float4 ov;                                                          \
        float* ovp = reinterpret_cast<float*>(&ov);                         \
        _Pragma("unroll")                                                   \
        for (int st = 0; st < 4; ++st) {                                    \
            /* 4 independent depth-4 chains: base -> +local -> +remote */   \
            u64 a0 = fma2(whhp[0][0], hL0, basep[st][0]);                   \
            u64 a1 = fma2(whhp[1][0], hL0, basep[st][1]);                   \
            u64 a2 = fma2(whhp[2][0], hL0, basep[st][2]);                   \
            u64 a3 = fma2(whhp[3][0], hL0, basep[st][3]);                   \
            a0 = fma2(whhp[0][1], hL1, a0);                                 \
            a1 = fma2(whhp[1][1], hL1, a1);                                 \
            a2 = fma2(whhp[2][1], hL1, a2);                                 \
            a3 = fma2(whhp[3][1], hL1, a3);                                 \
            a0 = fma2(whhp[0][2], hR0, a0);                                 \
            a1 = fma2(whhp[1][2], hR0, a1);                                 \
            a2 = fma2(whhp[2][2], hR0, a2);                                 \
            a3 = fma2(whhp[3][2], hR0, a3);                                 \
            a0 = fma2(whhp[0][3], hR1, a0);                                 \
            a1 = fma2(whhp[1][3], hR1, a1);                                 \
            a2 = fma2(whhp[2][3], hR1, a2);                                 \
            a3 = fma2(whhp[3][3], hR1, a3);                                 \
            float l0, h0_, l1, h1_, l2, h2_, l3, h3_;                       \
            upk2(a0, l0, h0_); upk2(a1, l1, h1_);                           \
            upk2(a2, l2, h2_); upk2(a3, l3, h3_);                           \
            t0 = tanh_ap(l0 + h0_);                                         \
            t1 = tanh_ap(l1 + h1_);                                         \
            t2 = tanh_ap(l2 + h2_);                                         \
            t3 = tanh_ap(l3 + h3_);                                         \
            /* exchange (shfl in flight while local packs + out-dot run) */ \
            const float s0 = __shfl_xor_sync(0xFFFFFFFFu, t0, 1);           \
            const float s1 = __shfl_xor_sync(0xFFFFFFFFu, t1, 1);           \
            const float s2 = __shfl_xor_sync(0xFFFFFFFFu, t2, 1);           \
            const float s3 = __shfl_xor_sync(0xFFFFFFFFu, t3, 1);           \
            hL0 = pk2(t0, t1);                                              \
            hL1 = pk2(t2, t3);                                              \
            u64 oa = fma2(wfcp[0], hL0, pk2(bo, 0.0f));                     \
            oa = fma2(wfcp[1], hL1, oa);                                    \
            hR0 = pk2(s0, s1);                                              \
            hR1 = pk2(s2, s3);                                              \
            oa = fma2(wfcp[2], hR0, oa);                                    \
            oa = fma2(wfcp[3], hR1, oa);                                    \
            float olo, ohi; upk2(oa, olo, ohi);                             \
            ovp[st] = olo + ohi;                                            \
        }                                                                   \
        if (half == 0)                                                      \
            *reinterpret_cast<float4*>(outp + (G) * 4) = ov;                \
    } while (0)

    const int NG = RNN_T / 4;  // 128 (even)
    for (int g = 0; g < NG; g += 2) {
        LOAD_GROUP(bufB, g + 1);
        if (g + 2 < NG) {
            const float4* pf = &xq[(size_t)(g + 2) * 7];
            asm volatile("prefetch.global.L2 [%0];" :: "l"(pf));
        }
        PROCESS_GROUP(bufA, g);
        if (g + 2 < NG) LOAD_GROUP(bufA, g + 2);
        if (g + 3 < NG) {
            const float4* pf = &xq[(size_t)(g + 3) * 7];
            asm volatile("prefetch.global.L2 [%0];" :: "l"(pf));
        }
        PROCESS_GROUP(bufB, g + 1);
    }

    // hidden [1, B, H]
    if (hidden) {
        float* hp = hidden + (size_t)b * RNN_H;
        const float tv[4] = { t0, t1, t2, t3 };
#pragma unroll
        for (int m = 0; m < 4; ++m) {
            const int r = base + m;
            if (r < RNN_H) hp[r] = tv[m];
        }
    }
#undef LOAD_GROUP
#undef PROCESS_GROUP
}

extern "C" void kernel_launch(void* const* d_in, const int* in_sizes, int n_in,
                              void* d_out, int out_size) {
    const float* x    = (const float*)d_in[0];
    const float* W_ih = (const float*)d_in[1];
    const float* W_hh = (const float*)d_in[2];
    const float* b_ih = (const float*)d_in[3];
    const float* b_hh = (const float*)d_in[4];
    const float* W_fc = (const float*)d_in[5];
    const float* b_fc = (const float*)d_in[6];

    float* out = (float*)d_out;
    float* hidden = nullptr;
    if (out_size >= RNN_B * RNN_T + RNN_B * RNN_H)
        hidden = out + (size_t)RNN_B * RNN_T;

    dim3 grid(RNN_B / 16);   // 512 single-warp blocks
    dim3 block(32);
    rnn_fused_kernel<<<grid, block>>>(x, W_ih, W_hh, b_ih, b_hh, W_fc, b_fc,
                                      out, hidden);
}

// round 4
// speedup vs baseline: 1.7155x; 1.1995x over previous
#include <cuda_runtime.h>

// RNN_43920335569315: vanilla tanh RNN. B=8192, T=512, I=H=7, O=1.
//   h_t = tanh(x_t W_ih^T + b_ih + b_hh + h_{t-1} W_hh^T);  out = h.W_fc + b_fc
// d_in = {x, W_ih, W_hh, b_ih, b_hh, W_fc, b_fc};  d_out = concat(out[B,T], h_T[1,B,H]).
//
// Round-4: 4 lanes per batch element (1024 warps, 4-warp blocks -> all SMSPs covered
// at ~1.73 warps/SMSP for TLP stall hiding). Lane owns 2 rows of the 8-padded H.
// Hidden state lives as one f32x2 pack per lane; exchanged with 3x 64-bit shfl.xor
// whose results feed fma2 directly (weights pre-reordered in xor order, no repack).

#define RNN_B 8192
#define RNN_T 512
#define RNN_H 7

typedef unsigned long long u64;

__device__ __forceinline__ u64 pk2(float lo, float hi) {
    u64 r; asm("mov.b64 %0, {%1, %2};" : "=l"(r) : "f"(lo), "f"(hi)); return r;
}
__device__ __forceinline__ void upk2(u64 v, float& lo, float& hi) {
    asm("mov.b64 {%0, %1}, %2;" : "=f"(lo), "=f"(hi) : "l"(v));
}
__device__ __forceinline__ u64 fma2(u64 a, u64 b, u64 c) {
    u64 d; asm("fma.rn.f32x2 %0, %1, %2, %3;" : "=l"(d) : "l"(a), "l"(b), "l"(c)); return d;
}
__device__ __forceinline__ float tanh_ap(float x) {
    float y; asm("tanh.approx.f32 %0, %1;" : "=f"(y) : "f"(x)); return y;
}

__global__ void __launch_bounds__(128, 1) rnn_fused_kernel(
    const float* __restrict__ x,
    const float* __restrict__ W_ih,
    const float* __restrict__ W_hh,
    const float* __restrict__ b_ih,
    const float* __restrict__ b_hh,
    const float* __restrict__ W_fc,
    const float* __restrict__ b_fc,
    float* __restrict__ out,
    float* __restrict__ hidden)
{
    const int tid = blockIdx.x * 128 + threadIdx.x;
    const int sub = tid & 3;          // which quarter of the (padded) H this lane owns
    const int b   = tid >> 2;         // batch element (4 consecutive lanes share one)

    const int r0 = 2 * sub;           // my rows: r0, r0+1  (row 7 is a zero pad)
    const int r1 = r0 + 1;

    // ---- weights ----
    // x-projection pairs in natural i-pair order p=(2p,2p+1):
    u64 wih_o[2][4];
    // recurrent + fc pairs in xor order j: pack j comes from lane sub^j and covers
    // k in {2*(sub^j), 2*(sub^j)+1}:
    u64 whh_o[2][4], wfc_o[4];
    float bias2[2];
#pragma unroll
    for (int m = 0; m < 2; ++m) {
        const int r = r0 + m;
        const bool ok = (r < RNN_H);
#pragma unroll
        for (int p = 0; p < 4; ++p) {
            const int i0 = 2 * p, i1 = 2 * p + 1;
            wih_o[m][p] = pk2((ok && i0 < RNN_H) ? __ldg(&W_ih[r * RNN_H + i0]) : 0.0f,
                              (ok && i1 < RNN_H) ? __ldg(&W_ih[r * RNN_H + i1]) : 0.0f);
            const int ps = sub ^ p;
            const int k0 = 2 * ps, k1 = 2 * ps + 1;
            whh_o[m][p] = pk2((ok && k0 < RNN_H) ? __ldg(&W_hh[r * RNN_H + k0]) : 0.0f,
                              (ok && k1 < RNN_H) ? __ldg(&W_hh[r * RNN_H + k1]) : 0.0f);
        }
        bias2[m] = ok ? (__ldg(&b_ih[r]) + __ldg(&b_hh[r])) : 0.0f;
    }
#pragma unroll
    for (int j = 0; j < 4; ++j) {
        const int ps = sub ^ j;
        const int k0 = 2 * ps, k1 = 2 * ps + 1;
        wfc_o[j] = pk2((k0 < RNN_H) ? __ldg(&W_fc[k0]) : 0.0f,
                       (k1 < RNN_H) ? __ldg(&W_fc[k1]) : 0.0f);
    }
    const u64 obias = pk2(__ldg(&b_fc[0]), 0.0f);

    const float4* __restrict__ xq =
        reinterpret_cast<const float4*>(x + (size_t)b * RNN_T * RNN_H);
    float* __restrict__ outp = out + (size_t)b * RNN_T;

    // State: my pack hP = (h_{2sub}, h_{2sub+1}); remote packs in xor order.
    u64 hP = 0, hX1 = 0, hX2 = 0, hX3 = 0;
    float t0 = 0.f, t1 = 0.f;

    float bufA[28], bufB[28];
#pragma unroll
    for (int q = 0; q < 7; ++q)
        reinterpret_cast<float4*>(bufA)[q] = __ldg(&xq[q]);

#define LOAD_GROUP(BUF, G) do {                                              \
        _Pragma("unroll")                                                    \
        for (int q = 0; q < 7; ++q)                                          \
            reinterpret_cast<float4*>(BUF)[q] = __ldg(&xq[(size_t)(G) * 7 + q]); \
    } while (0)

#define PROCESS_GROUP(BUF, G) do {                                          \
        /* horizontal base partials (bias in lo half) for all 4 steps:      \
           independent work ptxas can pour into tanh/shfl stalls */         \
        u64 basep[4][2];                                                    \
        _Pragma("unroll")                                                   \
        for (int st = 0; st < 4; ++st) {                                    \
            const float* xv = (BUF) + st * RNN_H;                           \
            const u64 xp0 = pk2(xv[0], xv[1]);                              \
            const u64 xp1 = pk2(xv[2], xv[3]);                              \
            const u64 xp2 = pk2(xv[4], xv[5]);                              \
            const u64 xp3 = pk2(xv[6], 0.0f);                               \
            _Pragma("unroll")                                               \
            for (int m = 0; m < 2; ++m) {                                   \
                u64 a = pk2(bias2[m], 0.0f);                                \
                a = fma2(wih_o[m][0], xp0, a);                              \
                a = fma2(wih_o[m][1], xp1, a);                              \
                a = fma2(wih_o[m][2], xp2, a);                              \
                a = fma2(wih_o[m][3], xp3, a);                              \
                basep[st][m] = a;                                           \
            }                                                               \
        }                                                                   \
        float4 ov;                                                          \
        float* ovp = reinterpret_cast<float*>(&ov);                         \
        _Pragma("unroll")                                                   \
        for (int st = 0; st < 4; ++st) {                                    \
            /* own pack first (ready immediately), shfl'd packs last */     \
            u64 a0 = fma2(whh_o[0][0], hP, basep[st][0]);                   \
            u64 a1 = fma2(whh_o[1][0], hP, basep[st][1]);                   \
            a0 = fma2(whh_o[0][1], hX1, a0);                                \
            a1 = fma2(whh_o[1][1], hX1, a1);                                \
            a0 = fma2(whh_o[0][2], hX2, a0);                                \
            a1 = fma2(whh_o[1][2], hX2, a1);                                \
            a0 = fma2(whh_o[0][3], hX3, a0);                                \
            a1 = fma2(whh_o[1][3], hX3, a1);                                \
            float l0, u0, l1, u1;                                           \
            upk2(a0, l0, u0); upk2(a1, l1, u1);                             \
            t0 = tanh_ap(l0 + u0);                                          \
            t1 = tanh_ap(l1 + u1);                                          \
            hP = pk2(t0, t1);                                               \
            hX1 = __shfl_xor_sync(0xFFFFFFFFu, hP, 1);                      \
            hX2 = __shfl_xor_sync(0xFFFFFFFFu, hP, 2);                      \
            hX3 = __shfl_xor_sync(0xFFFFFFFFu, hP, 3);                      \
            /* out-dot on the same packs (weights in xor order) */          \
            u64 oa = fma2(wfc_o[0], hP, obias);                             \
            oa = fma2(wfc_o[1], hX1, oa);                                   \
            oa = fma2(wfc_o[2], hX2, oa);                                   \
            oa = fma2(wfc_o[3], hX3, oa);                                   \
            float olo, ohi; upk2(oa, olo, ohi);                             \
            ovp[st] = olo + ohi;                                            \
        }                                                                   \
        if (sub == 0)                                                       \
            *reinterpret_cast<float4*>(outp + (G) * 4) = ov;                \
    } while (0)

    const int NG = RNN_T / 4;  // 128 (even)
    for (int g = 0; g < NG; g += 2) {
        LOAD_GROUP(bufB, g + 1);
        if (g + 2 < NG) {
            const float4* pf = &xq[(size_t)(g + 2) * 7];
            asm volatile("prefetch.global.L2 [%0];" :: "l"(pf));
        }
        PROCESS_GROUP(bufA, g);
        if (g + 2 < NG) LOAD_GROUP(bufA, g + 2);
        if (g + 3 < NG) {
            const float4* pf = &xq[(size_t)(g + 3) * 7];
            asm volatile("prefetch.global.L2 [%0];" :: "l"(pf));
        }
        PROCESS_GROUP(bufB, g + 1);
    }

    // hidden [1, B, H]: each lane writes its own real rows
    if (hidden) {
        float* hp = hidden + (size_t)b * RNN_H;
        hp[r0] = t0;                       // r0 = 0,2,4,6 -> always real
        if (r1 < RNN_H) hp[r1] = t1;       // skip pad row 7 (sub==3)
    }
#undef LOAD_GROUP
#undef PROCESS_GROUP
}

extern "C" void kernel_launch(void* const* d_in, const int* in_sizes, int n_in,
                              void* d_out, int out_size) {
    const float* x    = (const float*)d_in[0];
    const float* W_ih = (const float*)d_in[1];
    const float* W_hh = (const float*)d_in[2];
    const float* b_ih = (const float*)d_in[3];
    const float* b_hh = (const float*)d_in[4];
    const float* W_fc = (const float*)d_in[5];
    const float* b_fc = (const float*)d_in[6];

    float* out = (float*)d_out;
    float* hidden = nullptr;
    if (out_size >= RNN_B * RNN_T + RNN_B * RNN_H)
        hidden = out + (size_t)RNN_B * RNN_T;

    // 8192 elements x 4 lanes = 32768 threads; 128-thread blocks (4 warps)
    // -> 256 blocks, 1024 warps, every SMSP covered with ~1.73 warps.
    dim3 grid((RNN_B * 4) / 128);
    dim3 block(128);
    rnn_fused_kernel<<<grid, block>>>(x, W_ih, W_hh, b_ih, b_hh, W_fc, b_fc,
                                      out, hidden);
}